// round 8
// baseline (speedup 1.0000x reference)
#include <cuda_runtime.h>
#include <cstdint>

#define INC   64
#define DDIM  24
#define BATCH 16
#define DSP   (DDIM*DDIM*DDIM)      // 13824
#define NPOS  (BATCH*DSP)           // 221184
#define ODIM  47

// Halo'd B layout: per (b,k) a 26x26x26 grid, interior = 24^3, halo = zeros.
#define HROW  26
#define HSL   (26*26)               // 676
#define DSPH  (26*26*26)            // 17576
#define BTOT  ((size_t)BATCH * 27 * DSPH)   // 7,592,832 floats (~30.4 MB)

__device__ float g_B[BTOT];

// ---- packed f32x2 helpers ----
__device__ __forceinline__ unsigned long long pack2(float lo, float hi) {
    unsigned long long r;
    asm("mov.b64 %0, {%1, %2};" : "=l"(r) : "f"(lo), "f"(hi));
    return r;
}
__device__ __forceinline__ void unpack2(unsigned long long v, float& lo, float& hi) {
    asm("mov.b64 {%0, %1}, %2;" : "=f"(lo), "=f"(hi) : "l"(v));
}
__device__ __forceinline__ unsigned long long fma2(unsigned long long a,
                                                   unsigned long long b,
                                                   unsigned long long c) {
    unsigned long long d;
    asm("fma.rn.f32x2 %0, %1, %2, %3;" : "=l"(d) : "l"(a), "l"(b), "l"(c));
    return d;
}

// ============================================================
// Halo zero: write 0 to boundary cells of every (b,k) 26^3 grid.
// Interior cells untouched (pass1 overwrites them every launch).
// ============================================================
__global__ void __launch_bounds__(256) halo_zero() {
    const size_t i = (size_t)blockIdx.x * 256 + threadIdx.x;
    if (i >= BTOT) return;
    const int cell = (int)(i % DSPH);
    const int z = cell / HSL;
    const int r = cell - z * HSL;
    const int y = r / HROW;
    const int x = r - y * HROW;
    if (z == 0 || z == 25 || y == 0 || y == 25 || x == 0 || x == 25)
        g_B[i] = 0.0f;
}

// ============================================================
// Pass 1: B[b,k,z+1,y+1,x+1] = sum_c x[b,c,z,y,x] * W[c,0,k]
// 2 spatial positions per thread, 14 u64 f32x2 accumulators.
// (R2 design — measured at the fp32 FMA-pipe floor.)
// ============================================================
__global__ void __launch_bounds__(256) conv_pass1(const float* __restrict__ x,
                                                  const float* __restrict__ w) {
    __shared__ __align__(16) float sW[64 * 28];   // rows of 28 floats (27 + pad)
    const int tid = threadIdx.x;
    for (int idx = tid; idx < 64 * 27; idx += 256) {
        int c = idx / 27, k = idx - c * 27;
        sW[c * 28 + k] = w[c * 1728 + k];   // W[c][0][k]
    }
    if (tid < 64) sW[tid * 28 + 27] = 0.0f;
    __syncthreads();

    const int p0 = blockIdx.x * 512 + tid;   // 512 | DSP -> both pos same batch
    const int b  = p0 / DSP;
    const int sp0 = p0 - b * DSP;
    const int sp1 = sp0 + 256;
    const float* xp = x + (size_t)b * INC * DSP + sp0;

    unsigned long long a0[14], a1[14];
#pragma unroll
    for (int j = 0; j < 14; j++) { a0[j] = 0ull; a1[j] = 0ull; }

#pragma unroll 4
    for (int c = 0; c < INC; c++) {
        const float xv0 = xp[(size_t)c * DSP];
        const float xv1 = xp[(size_t)c * DSP + 256];
        const unsigned long long x20 = pack2(xv0, xv0);
        const unsigned long long x21 = pack2(xv1, xv1);
        const ulonglong2* wrow = (const ulonglong2*)(&sW[c * 28]);
#pragma unroll
        for (int j = 0; j < 7; j++) {
            ulonglong2 wp = wrow[j];
            a0[2 * j]     = fma2(x20, wp.x, a0[2 * j]);
            a1[2 * j]     = fma2(x21, wp.x, a1[2 * j]);
            a0[2 * j + 1] = fma2(x20, wp.y, a0[2 * j + 1]);
            a1[2 * j + 1] = fma2(x21, wp.y, a1[2 * j + 1]);
        }
    }

    // halo-layout indices for the two positions
    int z0 = sp0 / 576, r0 = sp0 - z0 * 576, y0 = r0 / 24, x0 = r0 - y0 * 24;
    int z1 = sp1 / 576, r1 = sp1 - z1 * 576, y1 = r1 / 24, x1 = r1 - y1 * 24;
    const int h0 = ((z0 + 1) * HROW + (y0 + 1)) * HROW + (x0 + 1);
    const int h1 = ((z1 + 1) * HROW + (y1 + 1)) * HROW + (x1 + 1);
    float* Bb = g_B + (size_t)b * 27 * DSPH;

#pragma unroll
    for (int j = 0; j < 14; j++) {
        float l0, hh0, l1, hh1;
        unpack2(a0[j], l0, hh0);
        unpack2(a1[j], l1, hh1);
        const int k0 = 2 * j;
        Bb[(size_t)k0 * DSPH + h0] = l0;
        Bb[(size_t)k0 * DSPH + h1] = l1;
        if (k0 + 1 < 27) {
            Bb[(size_t)(k0 + 1) * DSPH + h0] = hh0;
            Bb[(size_t)(k0 + 1) * DSPH + h1] = hh1;
        }
    }
}

// ============================================================
// Pass 2: one thread = one 2x2x2 output octet. Halo'd B makes
// every one of the 125 loads unconditional (no predication).
// Per iz-slab: 25 batched loads (MLP=25) -> separable sums.
// ============================================================
__global__ void __launch_bounds__(256) conv_pass2(const float* __restrict__ bias,
                                                  float* __restrict__ out) {
    int t = blockIdx.x * 256 + threadIdx.x;   // grid = 221184/256 = 864
    const int qx = t % 24; t /= 24;
    const int qy = t % 24; t /= 24;
    const int qz = t % 24;
    const int b  = t / 24;

    const float* __restrict__ Bb = g_B + (size_t)b * 27 * DSPH;

    // per-dim (weight tap, position delta) pairs; halo shift +1 absorbed
    const int wiT[5]   = {2, 0, 1, 2, 0};
    const int dposT[5] = {0, 1, 1, 1, 2};   // = dpos + 1 (halo shift)

    int zoff[5], yoff[5], xoff[5];
#pragma unroll
    for (int i = 0; i < 5; i++) {
        zoff[i] = wiT[i] * 9 * DSPH + (qz + dposT[i]) * HSL;
        yoff[i] = wiT[i] * 3 * DSPH + (qy + dposT[i]) * HROW;
        xoff[i] = wiT[i] * DSPH + (qx + dposT[i]);
    }

    float o8[2][2][2];
#pragma unroll
    for (int a = 0; a < 2; a++)
#pragma unroll
        for (int c = 0; c < 2; c++)
#pragma unroll
            for (int d = 0; d < 2; d++) o8[a][c][d] = 0.0f;

#pragma unroll
    for (int iz = 0; iz < 5; iz++) {
        float v[25];
#pragma unroll
        for (int iy = 0; iy < 5; iy++) {
            const int base = zoff[iz] + yoff[iy];
#pragma unroll
            for (int ix = 0; ix < 5; ix++)
                v[iy * 5 + ix] = __ldg(Bb + base + xoff[ix]);
        }
        float ys[2][2] = {{0.0f, 0.0f}, {0.0f, 0.0f}};
#pragma unroll
        for (int iy = 0; iy < 5; iy++) {
            const float xs0 = v[iy * 5 + 0] + v[iy * 5 + 1] + v[iy * 5 + 2];
            const float xs1 = v[iy * 5 + 2] + v[iy * 5 + 3] + v[iy * 5 + 4];
            if (iy <= 2) { ys[0][0] += xs0; ys[0][1] += xs1; }
            if (iy >= 2) { ys[1][0] += xs0; ys[1][1] += xs1; }
        }
        if (iz <= 2) {
#pragma unroll
            for (int c = 0; c < 2; c++)
#pragma unroll
                for (int d = 0; d < 2; d++) o8[0][c][d] += ys[c][d];
        }
        if (iz >= 2) {
#pragma unroll
            for (int c = 0; c < 2; c++)
#pragma unroll
                for (int d = 0; d < 2; d++) o8[1][c][d] += ys[c][d];
        }
    }

    const float bv = __ldg(bias);
    const int oz0 = 2 * qz, oy0 = 2 * qy, ox0 = 2 * qx;
#pragma unroll
    for (int pz = 0; pz < 2; pz++) {
        if (oz0 + pz >= ODIM) continue;
#pragma unroll
        for (int py = 0; py < 2; py++) {
            if (oy0 + py >= ODIM) continue;
            const long rbase = (((long)b * ODIM + oz0 + pz) * ODIM + oy0 + py) * ODIM;
#pragma unroll
            for (int pw = 0; pw < 2; pw++) {
                if (ox0 + pw >= ODIM) continue;
                out[rbase + ox0 + pw] = (o8[pz][py][pw] + bv) * 64.0f;
            }
        }
    }
}

extern "C" void kernel_launch(void* const* d_in, const int* in_sizes, int n_in,
                              void* d_out, int out_size) {
    const float* x    = (const float*)d_in[0];
    const float* w    = (const float*)d_in[1];
    const float* bias = (const float*)d_in[2];
    float* out = (float*)d_out;

    halo_zero<<<(int)((BTOT + 255) / 256), 256>>>();   // ~1 us, boundary only
    conv_pass1<<<NPOS / 512, 256>>>(x, w);             // 432 blocks
    conv_pass2<<<NPOS / 256, 256>>>(bias, out);        // 864 blocks
}

// round 9
// speedup vs baseline: 1.2316x; 1.2316x over previous
#include <cuda_runtime.h>
#include <cstdint>

#define INC   64
#define DDIM  24
#define BATCH 16
#define DSP   (DDIM*DDIM*DDIM)      // 13824
#define NPOS  (BATCH*DSP)           // 221184
#define ODIM  47

// Halo'd B layout: per (b,k) a 26x26x26 grid, interior = 24^3, halo = zeros.
#define HROW  26
#define HSL   (26*26)               // 676
#define DSPH  (26*26*26)            // 17576
#define NBK   (BATCH*27)            // 432 (b,k) grids
#define HALO_PER_GRID 3752          // 26^3 - 24^3
#define BTOT  ((size_t)NBK * DSPH)

__device__ float g_B[BTOT];

// ---- packed f32x2 helpers ----
__device__ __forceinline__ unsigned long long pack2(float lo, float hi) {
    unsigned long long r;
    asm("mov.b64 %0, {%1, %2};" : "=l"(r) : "f"(lo), "f"(hi));
    return r;
}
__device__ __forceinline__ void unpack2(unsigned long long v, float& lo, float& hi) {
    asm("mov.b64 {%0, %1}, %2;" : "=f"(lo), "=f"(hi) : "l"(v));
}
__device__ __forceinline__ unsigned long long fma2(unsigned long long a,
                                                   unsigned long long b,
                                                   unsigned long long c) {
    unsigned long long d;
    asm("fma.rn.f32x2 %0, %1, %2, %3;" : "=l"(d) : "l"(a), "l"(b), "l"(c));
    return d;
}

// ============================================================
// Halo zero: enumerate ONLY the 3752 boundary cells per (b,k)
// grid. 1.62M threads, every one does a useful store.
// ============================================================
__global__ void __launch_bounds__(256) halo_zero() {
    const int i = blockIdx.x * 256 + threadIdx.x;
    if (i >= NBK * HALO_PER_GRID) return;
    const int bk = i / HALO_PER_GRID;
    const int ci = i - bk * HALO_PER_GRID;

    int z, y, x;
    if (ci < 1352) {                 // z = 0 / z = 25 full slabs
        z = (ci < 676) ? 0 : 25;
        const int p = (ci < 676) ? ci : ci - 676;
        y = p / 26;
        x = p - y * 26;
    } else {                         // ring cells of slabs z = 1..24
        const int r = ci - 1352;
        z = r / 100 + 1;
        const int p = r - (z - 1) * 100;
        if (p < 52) { y = (p < 26) ? 0 : 25; x = (p < 26) ? p : p - 26; }
        else        { const int q = p - 52; x = (q < 24) ? 0 : 25; y = 1 + (q % 24); }
    }
    g_B[(size_t)bk * DSPH + (z * HROW + y) * HROW + x] = 0.0f;
}

// ============================================================
// Pass 1: B[b,k,z+1,y+1,x+1] = sum_c x[b,c,z,y,x] * W[c,0,k]
// 2 spatial positions per thread, 14 u64 f32x2 accumulators.
// (measured at the fp32 FMA-pipe floor)
// ============================================================
__global__ void __launch_bounds__(256) conv_pass1(const float* __restrict__ x,
                                                  const float* __restrict__ w) {
    __shared__ __align__(16) float sW[64 * 28];
    const int tid = threadIdx.x;
    for (int idx = tid; idx < 64 * 27; idx += 256) {
        int c = idx / 27, k = idx - c * 27;
        sW[c * 28 + k] = w[c * 1728 + k];   // W[c][0][k]
    }
    if (tid < 64) sW[tid * 28 + 27] = 0.0f;
    __syncthreads();

    const int p0 = blockIdx.x * 512 + tid;   // 512 | DSP -> both pos same batch
    const int b  = p0 / DSP;
    const int sp0 = p0 - b * DSP;
    const int sp1 = sp0 + 256;
    const float* xp = x + (size_t)b * INC * DSP + sp0;

    unsigned long long a0[14], a1[14];
#pragma unroll
    for (int j = 0; j < 14; j++) { a0[j] = 0ull; a1[j] = 0ull; }

#pragma unroll 4
    for (int c = 0; c < INC; c++) {
        const float xv0 = xp[(size_t)c * DSP];
        const float xv1 = xp[(size_t)c * DSP + 256];
        const unsigned long long x20 = pack2(xv0, xv0);
        const unsigned long long x21 = pack2(xv1, xv1);
        const ulonglong2* wrow = (const ulonglong2*)(&sW[c * 28]);
#pragma unroll
        for (int j = 0; j < 7; j++) {
            ulonglong2 wp = wrow[j];
            a0[2 * j]     = fma2(x20, wp.x, a0[2 * j]);
            a1[2 * j]     = fma2(x21, wp.x, a1[2 * j]);
            a0[2 * j + 1] = fma2(x20, wp.y, a0[2 * j + 1]);
            a1[2 * j + 1] = fma2(x21, wp.y, a1[2 * j + 1]);
        }
    }

    int z0 = sp0 / 576, r0 = sp0 - z0 * 576, y0 = r0 / 24, x0 = r0 - y0 * 24;
    int z1 = sp1 / 576, r1 = sp1 - z1 * 576, y1 = r1 / 24, x1 = r1 - y1 * 24;
    const int h0 = ((z0 + 1) * HROW + (y0 + 1)) * HROW + (x0 + 1);
    const int h1 = ((z1 + 1) * HROW + (y1 + 1)) * HROW + (x1 + 1);
    float* Bb = g_B + (size_t)b * 27 * DSPH;

#pragma unroll
    for (int j = 0; j < 14; j++) {
        float l0, hh0, l1, hh1;
        unpack2(a0[j], l0, hh0);
        unpack2(a1[j], l1, hh1);
        const int k0 = 2 * j;
        Bb[(size_t)k0 * DSPH + h0] = l0;
        Bb[(size_t)k0 * DSPH + h1] = l1;
        if (k0 + 1 < 27) {
            Bb[(size_t)(k0 + 1) * DSPH + h0] = hh0;
            Bb[(size_t)(k0 + 1) * DSPH + h1] = hh1;
        }
    }
}

// ============================================================
// Pass 2: one thread = TWO z-adjacent octets (16 outputs).
// Union of z-(pos,tap) rows over the pair is 8 (vs 2x5):
//   r: dz(+halo) wz    used by:
//   0:   0       w2    g0e
//   1:   1       w0    g0e
//   2:   1       w1    g0e g0o
//   3:   1       w2        g0o g1e
//   4:   2       w0        g0o g1e
//   5:   2       w1            g1e g1o
//   6:   2       w2                g1o
//   7:   3       w0                g1o
// 200 unconditional loads -> 16 outputs (12.5 LDG/out).
// ============================================================
__global__ void __launch_bounds__(256) conv_pass2(const float* __restrict__ bias,
                                                  float* __restrict__ out) {
    int t = blockIdx.x * 256 + threadIdx.x;   // 110592 threads = 432 blocks
    const int qx  = t % 24; t /= 24;
    const int qy  = t % 24; t /= 24;
    const int qzp = t % 12; t /= 12;
    const int b   = t;
    const int qz  = 2 * qzp;

    const float* __restrict__ Bb = g_B + (size_t)b * 27 * DSPH;

    // y/x per-dim (tap, pos+1) pairs (same as before, halo shift absorbed)
    const int wiT[5]   = {2, 0, 1, 2, 0};
    const int dposT[5] = {0, 1, 1, 1, 2};

    int yoff[5], xoff[5];
#pragma unroll
    for (int i = 0; i < 5; i++) {
        yoff[i] = wiT[i] * 3 * DSPH + (qy + dposT[i]) * HROW;
        xoff[i] = wiT[i] * DSPH + (qx + dposT[i]);
    }

    // z rows
    const int zdT[8] = {0, 1, 1, 1, 2, 2, 2, 3};
    const int zwT[8] = {2, 0, 1, 2, 0, 1, 2, 0};

    // 4 z-groups of [py][px] accumulators
    float g0e[2][2] = {{0,0},{0,0}}, g0o[2][2] = {{0,0},{0,0}};
    float g1e[2][2] = {{0,0},{0,0}}, g1o[2][2] = {{0,0},{0,0}};

#pragma unroll
    for (int r = 0; r < 8; r++) {
        const int zoff = zwT[r] * 9 * DSPH + (qz + zdT[r]) * HSL;

        float v[25];
#pragma unroll
        for (int iy = 0; iy < 5; iy++) {
            const int base = zoff + yoff[iy];
#pragma unroll
            for (int ix = 0; ix < 5; ix++)
                v[iy * 5 + ix] = __ldg(Bb + base + xoff[ix]);
        }
        float ys[2][2] = {{0,0},{0,0}};
#pragma unroll
        for (int iy = 0; iy < 5; iy++) {
            const float xs0 = v[iy * 5 + 0] + v[iy * 5 + 1] + v[iy * 5 + 2];
            const float xs1 = v[iy * 5 + 2] + v[iy * 5 + 3] + v[iy * 5 + 4];
            if (iy <= 2) { ys[0][0] += xs0; ys[0][1] += xs1; }
            if (iy >= 2) { ys[1][0] += xs0; ys[1][1] += xs1; }
        }
        // accumulate into the z-groups this row feeds
        if (r <= 2) {        // g0e: rows 0,1,2
#pragma unroll
            for (int c = 0; c < 2; c++)
#pragma unroll
                for (int d = 0; d < 2; d++) g0e[c][d] += ys[c][d];
        }
        if (r >= 2 && r <= 4) {   // g0o: rows 2,3,4
#pragma unroll
            for (int c = 0; c < 2; c++)
#pragma unroll
                for (int d = 0; d < 2; d++) g0o[c][d] += ys[c][d];
        }
        if (r >= 3 && r <= 5) {   // g1e: rows 3,4,5
#pragma unroll
            for (int c = 0; c < 2; c++)
#pragma unroll
                for (int d = 0; d < 2; d++) g1e[c][d] += ys[c][d];
        }
        if (r >= 5) {             // g1o: rows 5,6,7
#pragma unroll
            for (int c = 0; c < 2; c++)
#pragma unroll
                for (int d = 0; d < 2; d++) g1o[c][d] += ys[c][d];
        }
    }

    const float bv = __ldg(bias);
    const int oy0 = 2 * qy, ox0 = 2 * qx;

    // write 2 octets: octet o at qz+o, plane parity pz -> oz = 2*(qz+o)+pz
#pragma unroll
    for (int o = 0; o < 2; o++) {
#pragma unroll
        for (int pz = 0; pz < 2; pz++) {
            const int oz = 2 * (qz + o) + pz;
            if (oz >= ODIM) continue;
            const float (*g)[2] = (o == 0) ? (pz == 0 ? g0e : g0o)
                                           : (pz == 0 ? g1e : g1o);
#pragma unroll
            for (int py = 0; py < 2; py++) {
                if (oy0 + py >= ODIM) continue;
                const long rbase = (((long)b * ODIM + oz) * ODIM + oy0 + py) * ODIM;
#pragma unroll
                for (int pw = 0; pw < 2; pw++) {
                    if (ox0 + pw >= ODIM) continue;
                    out[rbase + ox0 + pw] = (g[py][pw] + bv) * 64.0f;
                }
            }
        }
    }
}

extern "C" void kernel_launch(void* const* d_in, const int* in_sizes, int n_in,
                              void* d_out, int out_size) {
    const float* x    = (const float*)d_in[0];
    const float* w    = (const float*)d_in[1];
    const float* bias = (const float*)d_in[2];
    float* out = (float*)d_out;

    halo_zero<<<(NBK * HALO_PER_GRID + 255) / 256, 256>>>();  // 6332 blocks, ~1 us
    conv_pass1<<<NPOS / 512, 256>>>(x, w);                    // 432 blocks
    conv_pass2<<<NPOS / 512, 256>>>(bias, out);               // 432 blocks
}

// round 10
// speedup vs baseline: 1.3593x; 1.1037x over previous
#include <cuda_runtime.h>
#include <cstdint>

#define INC   64
#define DDIM  24
#define BATCH 16
#define DSP   (DDIM*DDIM*DDIM)      // 13824
#define NPOS  (BATCH*DSP)           // 221184
#define ODIM  47

// Halo'd B layout: per (b,k) a 26x26x26 grid, interior = 24^3.
// Halo cells are NEVER written: __device__ globals are zero-initialized
// (.bss) at module load, and pass1 touches interior cells only, so the
// halo stays zero across all launches/replays. No zeroing kernel needed.
#define HROW  26
#define HSL   (26*26)               // 676
#define DSPH  (26*26*26)            // 17576
#define NBK   (BATCH*27)            // 432 (b,k) grids
#define BTOT  ((size_t)NBK * DSPH)

__device__ float g_B[BTOT];

// ---- packed f32x2 helpers ----
__device__ __forceinline__ unsigned long long pack2(float lo, float hi) {
    unsigned long long r;
    asm("mov.b64 %0, {%1, %2};" : "=l"(r) : "f"(lo), "f"(hi));
    return r;
}
__device__ __forceinline__ void unpack2(unsigned long long v, float& lo, float& hi) {
    asm("mov.b64 {%0, %1}, %2;" : "=f"(lo), "=f"(hi) : "l"(v));
}
__device__ __forceinline__ unsigned long long fma2(unsigned long long a,
                                                   unsigned long long b,
                                                   unsigned long long c) {
    unsigned long long d;
    asm("fma.rn.f32x2 %0, %1, %2, %3;" : "=l"(d) : "l"(a), "l"(b), "l"(c));
    return d;
}

// ============================================================
// Pass 1: B[b,k,z+1,y+1,x+1] = sum_c x[b,c,z,y,x] * W[c,0,k]
// 2 spatial positions per thread, 14 u64 f32x2 accumulators.
// (measured at the fp32 FMA-pipe floor)
// ============================================================
__global__ void __launch_bounds__(256) conv_pass1(const float* __restrict__ x,
                                                  const float* __restrict__ w) {
    __shared__ __align__(16) float sW[64 * 28];
    const int tid = threadIdx.x;
    for (int idx = tid; idx < 64 * 27; idx += 256) {
        int c = idx / 27, k = idx - c * 27;
        sW[c * 28 + k] = w[c * 1728 + k];   // W[c][0][k]
    }
    if (tid < 64) sW[tid * 28 + 27] = 0.0f;
    __syncthreads();

    const int p0 = blockIdx.x * 512 + tid;   // 512 | DSP -> both pos same batch
    const int b  = p0 / DSP;
    const int sp0 = p0 - b * DSP;
    const int sp1 = sp0 + 256;
    const float* xp = x + (size_t)b * INC * DSP + sp0;

    unsigned long long a0[14], a1[14];
#pragma unroll
    for (int j = 0; j < 14; j++) { a0[j] = 0ull; a1[j] = 0ull; }

#pragma unroll 4
    for (int c = 0; c < INC; c++) {
        const float xv0 = xp[(size_t)c * DSP];
        const float xv1 = xp[(size_t)c * DSP + 256];
        const unsigned long long x20 = pack2(xv0, xv0);
        const unsigned long long x21 = pack2(xv1, xv1);
        const ulonglong2* wrow = (const ulonglong2*)(&sW[c * 28]);
#pragma unroll
        for (int j = 0; j < 7; j++) {
            ulonglong2 wp = wrow[j];
            a0[2 * j]     = fma2(x20, wp.x, a0[2 * j]);
            a1[2 * j]     = fma2(x21, wp.x, a1[2 * j]);
            a0[2 * j + 1] = fma2(x20, wp.y, a0[2 * j + 1]);
            a1[2 * j + 1] = fma2(x21, wp.y, a1[2 * j + 1]);
        }
    }

    int z0 = sp0 / 576, r0 = sp0 - z0 * 576, y0 = r0 / 24, x0 = r0 - y0 * 24;
    int z1 = sp1 / 576, r1 = sp1 - z1 * 576, y1 = r1 / 24, x1 = r1 - y1 * 24;
    const int h0 = ((z0 + 1) * HROW + (y0 + 1)) * HROW + (x0 + 1);
    const int h1 = ((z1 + 1) * HROW + (y1 + 1)) * HROW + (x1 + 1);
    float* Bb = g_B + (size_t)b * 27 * DSPH;

#pragma unroll
    for (int j = 0; j < 14; j++) {
        float l0, hh0, l1, hh1;
        unpack2(a0[j], l0, hh0);
        unpack2(a1[j], l1, hh1);
        const int k0 = 2 * j;
        Bb[(size_t)k0 * DSPH + h0] = l0;
        Bb[(size_t)k0 * DSPH + h1] = l1;
        if (k0 + 1 < 27) {
            Bb[(size_t)(k0 + 1) * DSPH + h0] = hh0;
            Bb[(size_t)(k0 + 1) * DSPH + h1] = hh1;
        }
    }
}

// ============================================================
// Pass 2: one thread = TWO z-adjacent octets (16 outputs).
// Union of z-(pos,tap) rows over the pair is 8 (vs 2x5).
// 200 unconditional loads -> 16 outputs (12.5 LDG/out).
// ============================================================
__global__ void __launch_bounds__(256) conv_pass2(const float* __restrict__ bias,
                                                  float* __restrict__ out) {
    int t = blockIdx.x * 256 + threadIdx.x;   // 110592 threads = 432 blocks
    const int qx  = t % 24; t /= 24;
    const int qy  = t % 24; t /= 24;
    const int qzp = t % 12; t /= 12;
    const int b   = t;
    const int qz  = 2 * qzp;

    const float* __restrict__ Bb = g_B + (size_t)b * 27 * DSPH;

    // y/x per-dim (tap, pos+1) pairs (halo shift absorbed)
    const int wiT[5]   = {2, 0, 1, 2, 0};
    const int dposT[5] = {0, 1, 1, 1, 2};

    int yoff[5], xoff[5];
#pragma unroll
    for (int i = 0; i < 5; i++) {
        yoff[i] = wiT[i] * 3 * DSPH + (qy + dposT[i]) * HROW;
        xoff[i] = wiT[i] * DSPH + (qx + dposT[i]);
    }

    // z rows: (z position delta incl. halo, z tap)
    const int zdT[8] = {0, 1, 1, 1, 2, 2, 2, 3};
    const int zwT[8] = {2, 0, 1, 2, 0, 1, 2, 0};

    // 4 z-groups of [py][px] accumulators
    float g0e[2][2] = {{0,0},{0,0}}, g0o[2][2] = {{0,0},{0,0}};
    float g1e[2][2] = {{0,0},{0,0}}, g1o[2][2] = {{0,0},{0,0}};

#pragma unroll
    for (int r = 0; r < 8; r++) {
        const int zoff = zwT[r] * 9 * DSPH + (qz + zdT[r]) * HSL;

        float v[25];
#pragma unroll
        for (int iy = 0; iy < 5; iy++) {
            const int base = zoff + yoff[iy];
#pragma unroll
            for (int ix = 0; ix < 5; ix++)
                v[iy * 5 + ix] = __ldg(Bb + base + xoff[ix]);
        }
        float ys[2][2] = {{0,0},{0,0}};
#pragma unroll
        for (int iy = 0; iy < 5; iy++) {
            const float xs0 = v[iy * 5 + 0] + v[iy * 5 + 1] + v[iy * 5 + 2];
            const float xs1 = v[iy * 5 + 2] + v[iy * 5 + 3] + v[iy * 5 + 4];
            if (iy <= 2) { ys[0][0] += xs0; ys[0][1] += xs1; }
            if (iy >= 2) { ys[1][0] += xs0; ys[1][1] += xs1; }
        }
        if (r <= 2) {
#pragma unroll
            for (int c = 0; c < 2; c++)
#pragma unroll
                for (int d = 0; d < 2; d++) g0e[c][d] += ys[c][d];
        }
        if (r >= 2 && r <= 4) {
#pragma unroll
            for (int c = 0; c < 2; c++)
#pragma unroll
                for (int d = 0; d < 2; d++) g0o[c][d] += ys[c][d];
        }
        if (r >= 3 && r <= 5) {
#pragma unroll
            for (int c = 0; c < 2; c++)
#pragma unroll
                for (int d = 0; d < 2; d++) g1e[c][d] += ys[c][d];
        }
        if (r >= 5) {
#pragma unroll
            for (int c = 0; c < 2; c++)
#pragma unroll
                for (int d = 0; d < 2; d++) g1o[c][d] += ys[c][d];
        }
    }

    const float bv = __ldg(bias);
    const int oy0 = 2 * qy, ox0 = 2 * qx;

#pragma unroll
    for (int o = 0; o < 2; o++) {
#pragma unroll
        for (int pz = 0; pz < 2; pz++) {
            const int oz = 2 * (qz + o) + pz;
            if (oz >= ODIM) continue;
            const float (*g)[2] = (o == 0) ? (pz == 0 ? g0e : g0o)
                                           : (pz == 0 ? g1e : g1o);
#pragma unroll
            for (int py = 0; py < 2; py++) {
                if (oy0 + py >= ODIM) continue;
                const long rbase = (((long)b * ODIM + oz) * ODIM + oy0 + py) * ODIM;
#pragma unroll
                for (int pw = 0; pw < 2; pw++) {
                    if (ox0 + pw >= ODIM) continue;
                    out[rbase + ox0 + pw] = (g[py][pw] + bv) * 64.0f;
                }
            }
        }
    }
}

extern "C" void kernel_launch(void* const* d_in, const int* in_sizes, int n_in,
                              void* d_out, int out_size) {
    const float* x    = (const float*)d_in[0];
    const float* w    = (const float*)d_in[1];
    const float* bias = (const float*)d_in[2];
    float* out = (float*)d_out;

    conv_pass1<<<NPOS / 512, 256>>>(x, w);      // 432 blocks
    conv_pass2<<<NPOS / 512, 256>>>(bias, out); // 432 blocks
}

// round 13
// speedup vs baseline: 1.4944x; 1.0994x over previous
#include <cuda_runtime.h>
#include <cuda_bf16.h>
#include <cstdint>

#define INC   64
#define DDIM  24
#define BATCH 16
#define DSP   (DDIM*DDIM*DDIM)      // 13824
#define NPOS  (BATCH*DSP)           // 221184
#define ODIM  47

// Halo'd B: per (b,k) a 26^3 grid; halo cells never written (zero .bss init).
#define HROW  26
#define HSL   (26*26)
#define DSPH  (26*26*26)            // 17576
#define BTOT  ((size_t)BATCH * 27 * DSPH)

__device__ float g_B[BTOT];

// ---------- helpers ----------
__device__ __forceinline__ uint32_t smem_u32(const void* p) {
    uint32_t a;
    asm("{ .reg .u64 t; cvta.to.shared.u64 t, %1; cvt.u32.u64 %0, t; }"
        : "=r"(a) : "l"(p));
    return a;
}
__device__ __forceinline__ uint32_t pack_bf(__nv_bfloat16 lo, __nv_bfloat16 hi) {
    return (uint32_t)__bfloat16_as_ushort(lo) | ((uint32_t)__bfloat16_as_ushort(hi) << 16);
}
__device__ __forceinline__ void ldsm_x4_t(uint32_t r[4], uint32_t addr) {
    asm volatile("ldmatrix.sync.aligned.m8n8.x4.trans.shared.b16 {%0,%1,%2,%3}, [%4];"
                 : "=r"(r[0]), "=r"(r[1]), "=r"(r[2]), "=r"(r[3]) : "r"(addr));
}
__device__ __forceinline__ void mma_bf16(float d[4], const uint32_t a[4],
                                         const uint32_t b0, const uint32_t b1) {
    asm volatile(
        "mma.sync.aligned.m16n8k16.row.col.f32.bf16.bf16.f32 "
        "{%0,%1,%2,%3}, {%4,%5,%6,%7}, {%8,%9}, {%0,%1,%2,%3};"
        : "+f"(d[0]), "+f"(d[1]), "+f"(d[2]), "+f"(d[3])
        : "r"(a[0]), "r"(a[1]), "r"(a[2]), "r"(a[3]), "r"(b0), "r"(b1));
}

// ============================================================
// Pass 1 (warp MMA): B[pos][tap] = sum_c x[b,c,pos] * W[c,0,tap]
// fp32 via bf16 3-term split: x1w1 + x1w2 + x2w1.
// CTA: 128 thr, 512 positions (4 subtiles x 128). Grid 432.
// A staged k-major T[c][m] bf16 in smem (swizzled 16B chunks),
// fragments via ldmatrix.x4.trans. W fragments in registers.
// ============================================================
__global__ void __launch_bounds__(128, 3)
conv_pass1_hmma(const float* __restrict__ x, const float* __restrict__ w) {
    // T1/T2: [64 k][128 m] bf16 = 16 KB each. Row = 256 B.
    __shared__ __align__(16) char sA1[64 * 256];
    __shared__ __align__(16) char sA2[64 * 256];
    const uint32_t sb1 = smem_u32(sA1);
    const uint32_t sb2 = smem_u32(sA2);

    const int tid  = threadIdx.x;
    const int lane = tid & 31;
    const int wid  = tid >> 5;

    // ---- W fragments (held in registers for whole CTA lifetime) ----
    // bw1/bw2[nt][j][r]: B-frag regs for n-tile nt, k-chunk j, reg r (k, k+8).
    uint32_t bw1[4][4][2], bw2[4][4][2];
    {
        const int n  = (lane >> 2);           // within-tile n
#pragma unroll
        for (int nt = 0; nt < 4; nt++) {
            const int ng = nt * 8 + n;
            const bool nok = ng < 27;
#pragma unroll
            for (int j = 0; j < 4; j++) {
#pragma unroll
                for (int r = 0; r < 2; r++) {
                    const int c0 = j * 16 + (lane & 3) * 2 + r * 8;
                    const float va = nok ? __ldg(w + c0 * 1728 + ng) : 0.0f;
                    const float vb = nok ? __ldg(w + (c0 + 1) * 1728 + ng) : 0.0f;
                    const __nv_bfloat16 a1 = __float2bfloat16(va);
                    const __nv_bfloat16 a2 = __float2bfloat16(va - __bfloat162float(a1));
                    const __nv_bfloat16 b1 = __float2bfloat16(vb);
                    const __nv_bfloat16 b2 = __float2bfloat16(vb - __bfloat162float(b1));
                    bw1[nt][j][r] = pack_bf(a1, b1);
                    bw2[nt][j][r] = pack_bf(a2, b2);
                }
            }
        }
    }

    const int p0  = blockIdx.x * 512;
    const int b   = p0 / DSP;
    const int spb = p0 - b * DSP;             // 512-aligned, all subtiles same b
    const float* __restrict__ xb0 = x + (size_t)b * INC * DSP;
    float* __restrict__ Bb = g_B + (size_t)b * 27 * DSPH;

    for (int s = 0; s < 4; s++) {
        const int sp0 = spb + s * 128;
        __syncthreads();   // protect smem from previous subtile's readers

        // ---- stage A: T[c][m] bf16 pairs, swizzled; LDG.64 coalesced ----
        const float* __restrict__ xb = xb0 + sp0;
        const int chalf = tid >> 6;           // 0/1
        const int m0    = (tid & 63) * 2;
#pragma unroll 4
        for (int c2 = 0; c2 < 32; c2++) {
            const int c = c2 * 2 + chalf;
            const float2 xv = __ldg((const float2*)(xb + (size_t)c * DSP + m0));
            const __nv_bfloat16 h1a = __float2bfloat16(xv.x);
            const __nv_bfloat16 h2a = __float2bfloat16(xv.x - __bfloat162float(h1a));
            const __nv_bfloat16 h1b = __float2bfloat16(xv.y);
            const __nv_bfloat16 h2b = __float2bfloat16(xv.y - __bfloat162float(h1b));
            const int off = c * 256 + ((((m0 >> 3) ^ (c & 7)) << 4)) + ((m0 & 7) * 2);
            *(uint32_t*)(sA1 + off) = pack_bf(h1a, h1b);
            *(uint32_t*)(sA2 + off) = pack_bf(h2a, h2b);
        }
        __syncthreads();

        // ---- compute: warp wid covers rows [32*wid, 32*wid+32) ----
#pragma unroll
        for (int half = 0; half < 2; half++) {
            const int mb = wid * 32 + half * 16;

            // A fragments via ldmatrix.x4.trans
            uint32_t fa1[4][4], fa2[4][4];
            const int sub = lane >> 3;
            const int mc  = mb + ((sub & 1) ? 8 : 0);
#pragma unroll
            for (int j = 0; j < 4; j++) {
                const int kr = j * 16 + ((sub & 2) ? 8 : 0) + (lane & 7);
                const uint32_t off = (uint32_t)(kr * 256 + (((mc >> 3) ^ (kr & 7)) << 4));
                ldsm_x4_t(fa1[j], sb1 + off);
                ldsm_x4_t(fa2[j], sb2 + off);
            }

            // halo indices for this thread's two D rows
            const int r0  = mb + (lane >> 2);
            const int spA = sp0 + r0, spB = sp0 + r0 + 8;
            int zA = spA / 576, rA = spA - zA * 576, yA = rA / 24, xA = rA - yA * 24;
            int zB = spB / 576, rB = spB - zB * 576, yB = rB / 24, xB = rB - yB * 24;
            const int hA = ((zA + 1) * HROW + (yA + 1)) * HROW + (xA + 1);
            const int hB = ((zB + 1) * HROW + (yB + 1)) * HROW + (xB + 1);

#pragma unroll
            for (int nt = 0; nt < 4; nt++) {
                float d[4] = {0.f, 0.f, 0.f, 0.f};
#pragma unroll
                for (int j = 0; j < 4; j++) mma_bf16(d, fa1[j], bw1[nt][j][0], bw1[nt][j][1]);
#pragma unroll
                for (int j = 0; j < 4; j++) mma_bf16(d, fa1[j], bw2[nt][j][0], bw2[nt][j][1]);
#pragma unroll
                for (int j = 0; j < 4; j++) mma_bf16(d, fa2[j], bw1[nt][j][0], bw1[nt][j][1]);

                const int t0 = nt * 8 + (lane & 3) * 2;
                const int t1 = t0 + 1;
                if (t0 < 27) {
                    Bb[(size_t)t0 * DSPH + hA] = d[0];
                    Bb[(size_t)t0 * DSPH + hB] = d[2];
                }
                if (t1 < 27) {
                    Bb[(size_t)t1 * DSPH + hA] = d[1];
                    Bb[(size_t)t1 * DSPH + hB] = d[3];
                }
            }
        }
    }
}

// ============================================================
// Pass 2: one thread = one 2x2x2 output octet (verified R7/R10).
// 125 unconditional loads (halo'd B), batched 25/slab, separable sums.
// ============================================================
__global__ void __launch_bounds__(256) conv_pass2(const float* __restrict__ bias,
                                                  float* __restrict__ out) {
    int t = blockIdx.x * 256 + threadIdx.x;   // grid = 864
    const int qx = t % 24; t /= 24;
    const int qy = t % 24; t /= 24;
    const int qz = t % 24;
    const int b  = t / 24;

    const float* __restrict__ Bb = g_B + (size_t)b * 27 * DSPH;

    const int wiT[5]   = {2, 0, 1, 2, 0};
    const int dposT[5] = {0, 1, 1, 1, 2};   // pos delta + halo shift

    int zoff[5], yoff[5], xoff[5];
#pragma unroll
    for (int i = 0; i < 5; i++) {
        zoff[i] = wiT[i] * 9 * DSPH + (qz + dposT[i]) * HSL;
        yoff[i] = wiT[i] * 3 * DSPH + (qy + dposT[i]) * HROW;
        xoff[i] = wiT[i] * DSPH + (qx + dposT[i]);
    }

    float o8[2][2][2];
#pragma unroll
    for (int a = 0; a < 2; a++)
#pragma unroll
        for (int c = 0; c < 2; c++)
#pragma unroll
            for (int d = 0; d < 2; d++) o8[a][c][d] = 0.0f;

#pragma unroll
    for (int iz = 0; iz < 5; iz++) {
        float v[25];
#pragma unroll
        for (int iy = 0; iy < 5; iy++) {
            const int base = zoff[iz] + yoff[iy];
#pragma unroll
            for (int ix = 0; ix < 5; ix++)
                v[iy * 5 + ix] = __ldg(Bb + base + xoff[ix]);
        }
        float ys[2][2] = {{0,0},{0,0}};
#pragma unroll
        for (int iy = 0; iy < 5; iy++) {
            const float xs0 = v[iy * 5 + 0] + v[iy * 5 + 1] + v[iy * 5 + 2];
            const float xs1 = v[iy * 5 + 2] + v[iy * 5 + 3] + v[iy * 5 + 4];
            if (iy <= 2) { ys[0][0] += xs0; ys[0][1] += xs1; }
            if (iy >= 2) { ys[1][0] += xs0; ys[1][1] += xs1; }
        }
        if (iz <= 2) {
#pragma unroll
            for (int c = 0; c < 2; c++)
#pragma unroll
                for (int d = 0; d < 2; d++) o8[0][c][d] += ys[c][d];
        }
        if (iz >= 2) {
#pragma unroll
            for (int c = 0; c < 2; c++)
#pragma unroll
                for (int d = 0; d < 2; d++) o8[1][c][d] += ys[c][d];
        }
    }

    const float bv = __ldg(bias);
    const int oz0 = 2 * qz, oy0 = 2 * qy, ox0 = 2 * qx;
#pragma unroll
    for (int pz = 0; pz < 2; pz++) {
        if (oz0 + pz >= ODIM) continue;
#pragma unroll
        for (int py = 0; py < 2; py++) {
            if (oy0 + py >= ODIM) continue;
            const long rbase = (((long)b * ODIM + oz0 + pz) * ODIM + oy0 + py) * ODIM;
#pragma unroll
            for (int pw = 0; pw < 2; pw++) {
                if (ox0 + pw >= ODIM) continue;
                out[rbase + ox0 + pw] = (o8[pz][py][pw] + bv) * 64.0f;
            }
        }
    }
}

extern "C" void kernel_launch(void* const* d_in, const int* in_sizes, int n_in,
                              void* d_out, int out_size) {
    const float* x    = (const float*)d_in[0];
    const float* w    = (const float*)d_in[1];
    const float* bias = (const float*)d_in[2];
    float* out = (float*)d_out;

    conv_pass1_hmma<<<NPOS / 512, 128>>>(x, w);   // 432 CTAs
    conv_pass2<<<NPOS / 256, 256>>>(bias, out);   // 864 CTAs
}